// round 14
// baseline (speedup 1.0000x reference)
#include <cuda_runtime.h>
#include <cuda_fp16.h>
#include <cuda_bf16.h>
#include <cstdint>

// ---------------------------------------------------------------------------
// SSLPretrainModel v11:
//   convert_a (A->fp16 stream) | then GEMM on main stream while
//   pool16 (fp16 segment sum) + graph_head run on side stream.
//   D = A16 @ W16; rel_err ~3e-4 << 1e-3.
// ---------------------------------------------------------------------------

#define H 512
#define AF 133
#define BF 14
#define NCOLS (AF + BF)      // 147
#define NPAD 160

#define MAX_N 204800
#define MAX_B 4608

__device__ float g_atom_proj[MAX_N * BF];
__device__ float g_graph_emb[MAX_B * H];
__device__ __align__(16) __half g_Wh[NPAD * H];           // W^T fp16 [160][512]
__device__ __align__(16) __half g_A16[(size_t)MAX_N * H]; // A fp16 [N][512]

// ---------------------------------------------------------------------------
// helpers
// ---------------------------------------------------------------------------
__device__ __forceinline__ uint32_t smem_u32(const void* p) {
    uint32_t a;
    asm("{ .reg .u64 t; cvta.to.shared.u64 t, %1; cvt.u32.u64 %0, t; }" : "=r"(a) : "l"(p));
    return a;
}

__device__ __forceinline__ uint32_t f16x2_pack(float lo_elem, float hi_elem) {
    uint32_t r;
    asm("cvt.rn.f16x2.f32 %0, %1, %2;" : "=r"(r) : "f"(hi_elem), "f"(lo_elem));
    return r;
}

__device__ __forceinline__ void mma16816(float& d0, float& d1, float& d2, float& d3,
                                         uint32_t a0, uint32_t a1, uint32_t a2, uint32_t a3,
                                         uint32_t b0, uint32_t b1) {
    asm volatile(
        "mma.sync.aligned.m16n8k16.row.col.f32.f16.f16.f32 "
        "{%0,%1,%2,%3}, {%4,%5,%6,%7}, {%8,%9}, {%0,%1,%2,%3};"
        : "+f"(d0), "+f"(d1), "+f"(d2), "+f"(d3)
        : "r"(a0), "r"(a1), "r"(a2), "r"(a3), "r"(b0), "r"(b1));
}

__device__ __forceinline__ void ldmx4(uint32_t& r0, uint32_t& r1, uint32_t& r2,
                                      uint32_t& r3, uint32_t addr) {
    asm volatile("ldmatrix.sync.aligned.m8n8.x4.shared.b16 {%0,%1,%2,%3}, [%4];"
                 : "=r"(r0), "=r"(r1), "=r"(r2), "=r"(r3) : "r"(addr));
}
__device__ __forceinline__ void ldmx2(uint32_t& r0, uint32_t& r1, uint32_t addr) {
    asm volatile("ldmatrix.sync.aligned.m8n8.x2.shared.b16 {%0,%1}, [%2];"
                 : "=r"(r0), "=r"(r1) : "r"(addr));
}

#define CP_ASYNC16(saddr, gptr) \
    asm volatile("cp.async.cg.shared.global [%0], [%1], 16;" :: "r"(saddr), "l"(gptr))
#define CP_COMMIT() asm volatile("cp.async.commit_group;" ::: "memory")
#define CP_WAIT0()  asm volatile("cp.async.wait_group 0;" ::: "memory")

// ---------------------------------------------------------------------------
// Kernel 0: pack fused W^T into fp16.
// ---------------------------------------------------------------------------
__global__ void pack_w(const float* __restrict__ Wn,
                       const float* __restrict__ We)
{
    int idx = blockIdx.x * 256 + threadIdx.x;
    if (idx >= NPAD * H) return;
    int n = idx >> 9;
    int k = idx & 511;
    float v = 0.f;
    if (n < AF)         v = Wn[k * AF + n];
    else if (n < NCOLS) v = We[k * BF + (n - AF)];
    g_Wh[idx] = __float2half_rn(v);
}

// ---------------------------------------------------------------------------
// Kernel 1: streaming A (fp32) -> g_A16 (fp16). 8 elems per thread-iter.
// ---------------------------------------------------------------------------
__global__ __launch_bounds__(256)
void convert_a(const float* __restrict__ A, long n8)
{
    long i = (long)blockIdx.x * 256 + threadIdx.x;
    long stride = (long)gridDim.x * 256;
    for (; i < n8; i += stride) {
        const float4* src = reinterpret_cast<const float4*>(A) + 2 * i;
        float4 v0 = src[0];
        float4 v1 = src[1];
        uint4 p;
        p.x = f16x2_pack(v0.x, v0.y);
        p.y = f16x2_pack(v0.z, v0.w);
        p.z = f16x2_pack(v1.x, v1.y);
        p.w = f16x2_pack(v1.z, v1.w);
        reinterpret_cast<uint4*>(g_A16)[i] = p;
    }
}

// ---------------------------------------------------------------------------
// Kernel 2: segment sum over sorted batch, reading fp16 A copy.
// One block per graph, 128 threads x 4 cols (uint2 = 4 halves).
// ---------------------------------------------------------------------------
__global__ __launch_bounds__(128)
void pool16(const int* __restrict__ batch, int N)
{
    const int g = blockIdx.x;

    int lo = 0, hi = N;
    while (lo < hi) { int m = (lo + hi) >> 1; if (batch[m] < g) lo = m + 1; else hi = m; }
    const int start = lo;
    hi = N;
    while (lo < hi) { int m = (lo + hi) >> 1; if (batch[m] < g + 1) lo = m + 1; else hi = m; }
    const int end = lo;

    const int t = threadIdx.x;
    float4 s0 = make_float4(0.f, 0.f, 0.f, 0.f);
    float4 s1 = make_float4(0.f, 0.f, 0.f, 0.f);
    int i = start;
    for (; i + 1 < end; i += 2) {
        uint2 p0 = reinterpret_cast<const uint2*>(g_A16 + (size_t)i * H)[t];
        uint2 p1 = reinterpret_cast<const uint2*>(g_A16 + (size_t)(i + 1) * H)[t];
        __half2 a0 = *reinterpret_cast<__half2*>(&p0.x);
        __half2 a1 = *reinterpret_cast<__half2*>(&p0.y);
        __half2 b0 = *reinterpret_cast<__half2*>(&p1.x);
        __half2 b1 = *reinterpret_cast<__half2*>(&p1.y);
        float2 f0 = __half22float2(a0), f1 = __half22float2(a1);
        float2 g0 = __half22float2(b0), g1 = __half22float2(b1);
        s0.x += f0.x; s0.y += f0.y; s0.z += f1.x; s0.w += f1.y;
        s1.x += g0.x; s1.y += g0.y; s1.z += g1.x; s1.w += g1.y;
    }
    if (i < end) {
        uint2 p0 = reinterpret_cast<const uint2*>(g_A16 + (size_t)i * H)[t];
        __half2 a0 = *reinterpret_cast<__half2*>(&p0.x);
        __half2 a1 = *reinterpret_cast<__half2*>(&p0.y);
        float2 f0 = __half22float2(a0), f1 = __half22float2(a1);
        s0.x += f0.x; s0.y += f0.y; s0.z += f1.x; s0.w += f1.y;
    }
    s0.x += s1.x; s0.y += s1.y; s0.z += s1.z; s0.w += s1.w;
    reinterpret_cast<float4*>(g_graph_emb + (size_t)g * H)[t] = s0;
}

// ---------------------------------------------------------------------------
// Kernel 3: HMMA GEMM  C[N,147] = A16[N,512] @ Wf (+bias epilogue)
// CTA 128x160, 256 threads, 2 CTAs/SM. Warp grid 2(m) x 4(n); warp tile 64x40.
// BK=64; all operands via cp.async.
// ---------------------------------------------------------------------------
#define BKC 64
#define PITCH 144
#define BM 128
#define A_TILE (BM * PITCH)                // 18432
#define B_TILE (160 * PITCH)               // 23040
#define OFF_A 0
#define OFF_B (A_TILE)
#define BUFB (A_TILE + B_TILE)             // 41472
#define SMEM_DYN (2 * BUFB)                // 82944
#define GT 256

__global__ __launch_bounds__(GT, 2)
void gemm_mma(const float* __restrict__ bn,
              const float* __restrict__ be,
              float* __restrict__ node_out,
              int N)
{
    extern __shared__ char dyn[];
    __shared__ float s_bias[NPAD];

    const int tid = threadIdx.x;
    const int wid = tid >> 5;
    const int lid = tid & 31;
    const int block_row = blockIdx.x * BM;
    const uint32_t sbase = smem_u32(dyn);

    if (tid < NPAD) {
        float b = 0.f;
        if (tid < AF) b = bn[tid];
        else if (tid < NCOLS) b = be[tid - AF];
        s_bias[tid] = b;
    }

    // A cp.async: 128 rows x 128B = 1024 x 16B ops -> 4 per thread
    const __half* asrc[4];
    uint32_t asmem[4];
    bool aact[4];
    #pragma unroll
    for (int i = 0; i < 4; i++) {
        int idx = tid + i * GT;
        int r  = idx >> 3;
        int j  = idx & 7;
        aact[i]  = (block_row + r < N);
        asrc[i]  = g_A16 + (size_t)(block_row + r) * H + j * 8;
        asmem[i] = (uint32_t)(OFF_A + r * PITCH + j * 16);
    }
    // B cp.async: 160 rows x 128B = 1280 x 16B ops -> 5 per thread
    const __half* bsrc[5];
    uint32_t bsmem[5];
    #pragma unroll
    for (int i = 0; i < 5; i++) {
        int idx = tid + i * GT;
        int r  = idx >> 3;
        int j  = idx & 7;
        bsrc[i]  = g_Wh + (size_t)r * H + j * 8;
        bsmem[i] = (uint32_t)(OFF_B + r * PITCH + j * 16);
    }

    auto cpAB = [&](int c, int buf) {
        const uint32_t bb = sbase + buf * BUFB;
        #pragma unroll
        for (int i = 0; i < 4; i++)
            if (aact[i]) CP_ASYNC16(bb + asmem[i], asrc[i] + c * BKC);
        #pragma unroll
        for (int i = 0; i < 5; i++)
            CP_ASYNC16(bb + bsmem[i], bsrc[i] + c * BKC);
        CP_COMMIT();
    };

    float acc[4][5][4];
    #pragma unroll
    for (int mt = 0; mt < 4; mt++)
        #pragma unroll
        for (int nt = 0; nt < 5; nt++)
            #pragma unroll
            for (int q = 0; q < 4; q++) acc[mt][nt][q] = 0.f;

    const int wm = wid & 1;
    const int wn = wid >> 1;
    const int g  = lid >> 2;
    const int t  = lid & 3;
    const int lid16 = lid & 15;

    const uint32_t a_lm = (uint32_t)((wm * 64 + lid16) * PITCH + (lid >> 4) * 16);
    uint32_t b_lm4[2];
    #pragma unroll
    for (int p = 0; p < 2; p++)
        b_lm4[p] = (uint32_t)((wn * 40 + p * 16 + (lid & 7) + ((lid >> 4) & 1) * 8) * PITCH
                              + ((lid >> 3) & 1) * 16);
    const uint32_t b_lm2 = (uint32_t)((wn * 40 + 32 + (lid16 & 7)) * PITCH
                                      + ((lid16 >> 3) & 1) * 16);

    cpAB(0, 0);
    CP_WAIT0();
    __syncthreads();

    const int NCH = H / BKC;   // 8
    for (int c = 0; c < NCH; c++) {
        const int buf = c & 1;
        const uint32_t base = sbase + buf * BUFB;

        if (c + 1 < NCH) cpAB(c + 1, buf ^ 1);

        #pragma unroll
        for (int ks = 0; ks < 4; ks++) {
            const uint32_t kb = ks * 32;
            uint32_t fa[4][4];
            #pragma unroll
            for (int mt = 0; mt < 4; mt++)
                ldmx4(fa[mt][0], fa[mt][1], fa[mt][2], fa[mt][3],
                      base + OFF_A + a_lm + mt * 16 * PITCH + kb);

            uint32_t bh[10];
            ldmx4(bh[0], bh[1], bh[2], bh[3], base + OFF_B + b_lm4[0] + kb);
            ldmx4(bh[4], bh[5], bh[6], bh[7], base + OFF_B + b_lm4[1] + kb);
            ldmx2(bh[8], bh[9],              base + OFF_B + b_lm2 + kb);

            #pragma unroll
            for (int nt = 0; nt < 5; nt++) {
                uint32_t h0 = bh[2*nt], h1 = bh[2*nt+1];
                #pragma unroll
                for (int mt = 0; mt < 4; mt++) {
                    float* d = acc[mt][nt];
                    mma16816(d[0],d[1],d[2],d[3],
                             fa[mt][0],fa[mt][1],fa[mt][2],fa[mt][3], h0, h1);
                }
            }
        }

        if (c + 1 < NCH) {
            CP_WAIT0();
            __syncthreads();
        }
    }

    #pragma unroll
    for (int mt = 0; mt < 4; mt++) {
        #pragma unroll
        for (int half = 0; half < 2; half++) {
            int row = block_row + wm * 64 + mt * 16 + g + half * 8;
            if (row >= N) continue;
            float* nrow = node_out + (size_t)row * AF;
            float* prow = g_atom_proj + (size_t)row * BF;
            #pragma unroll
            for (int nt = 0; nt < 5; nt++) {
                int col = wn * 40 + nt * 8 + 2 * t;
                float v0 = acc[mt][nt][2 * half + 0] + s_bias[col];
                float v1 = acc[mt][nt][2 * half + 1] + s_bias[col + 1];
                if (col < AF)          nrow[col] = v0;
                else if (col < NCOLS)  prow[col - AF] = v0;
                if (col + 1 < AF)          nrow[col + 1] = v1;
                else if (col + 1 < NCOLS)  prow[col + 1 - AF] = v1;
            }
        }
    }
}

// ---------------------------------------------------------------------------
// Kernel 4a: init graph output with b_g2
// ---------------------------------------------------------------------------
__global__ void init_graph_out(float* __restrict__ graph_out,
                               const float* __restrict__ bg2, int B)
{
    int g = blockIdx.x * blockDim.x + threadIdx.x;
    if (g < B) graph_out[g] = bg2[0];
}

// ---------------------------------------------------------------------------
// Kernel 4b: graph head (FFMA2)
// ---------------------------------------------------------------------------
__device__ __forceinline__ unsigned long long pack_dup(float a) {
    unsigned long long r;
    unsigned int ab = __float_as_uint(a);
    asm("mov.b64 %0, {%1, %1};" : "=l"(r) : "r"(ab));
    return r;
}
__device__ __forceinline__ void fma2(unsigned long long& d,
                                     unsigned long long a,
                                     unsigned long long b) {
    asm("fma.rn.f32x2 %0, %1, %2, %0;" : "+l"(d) : "l"(a), "l"(b));
}
__device__ __forceinline__ void unpack2(unsigned long long v, float& lo, float& hi) {
    unsigned int l, h;
    asm("mov.b64 {%0, %1}, %2;" : "=r"(l), "=r"(h) : "l"(v));
    lo = __uint_as_float(l);
    hi = __uint_as_float(h);
}

__global__ __launch_bounds__(256)
void graph_head(const float* __restrict__ Wg1,
                const float* __restrict__ bg1,
                const float* __restrict__ Wg2,
                float* __restrict__ graph_out,
                int B)
{
    __shared__ float Es[32][65];
    __shared__ float Ws2[32][132];

    const int brow = blockIdx.x * 64;
    const int bcol = blockIdx.y * 128;
    const int tid = threadIdx.x;
    const int tx = tid & 15;
    const int ty = tid >> 4;

    unsigned long long acc[4][4];
    #pragma unroll
    for (int i = 0; i < 4; i++)
        #pragma unroll
        for (int p = 0; p < 4; p++) acc[i][p] = 0ull;

    for (int k0 = 0; k0 < H; k0 += 32) {
        #pragma unroll
        for (int it = 0; it < 2; it++) {
            int i = tid + it * 256;
            int r  = i >> 3;
            int c4 = i & 7;
            int row = brow + r;
            float4 v = make_float4(0.f, 0.f, 0.f, 0.f);
            if (row < B)
                v = reinterpret_cast<const float4*>(g_graph_emb + (size_t)row * H + k0)[c4];
            Es[c4 * 4 + 0][r] = v.x;
            Es[c4 * 4 + 1][r] = v.y;
            Es[c4 * 4 + 2][r] = v.z;
            Es[c4 * 4 + 3][r] = v.w;
        }
        #pragma unroll
        for (int it = 0; it < 4; it++) {
            int i = tid + it * 256;
            int kk = i >> 5;
            int c4 = i & 31;
            float4 v = reinterpret_cast<const float4*>(Wg1 + (size_t)(k0 + kk) * H + bcol)[c4];
            *reinterpret_cast<float4*>(&Ws2[kk][c4 * 4]) = v;
        }
        __syncthreads();

        #pragma unroll 8
        for (int kk = 0; kk < 32; kk++) {
            unsigned long long b2[4];
            #pragma unroll
            for (int p = 0; p < 4; p++)
                b2[p] = *reinterpret_cast<const unsigned long long*>(&Ws2[kk][2 * tx + 32 * p]);
            #pragma unroll
            for (int i = 0; i < 4; i++) {
                unsigned long long a2 = pack_dup(Es[kk][ty + 16 * i]);
                #pragma unroll
                for (int p = 0; p < 4; p++)
                    fma2(acc[i][p], a2, b2[p]);
            }
        }
        __syncthreads();
    }

    float part[4] = {0.f, 0.f, 0.f, 0.f};
    #pragma unroll
    for (int p = 0; p < 4; p++) {
        int c0 = bcol + 2 * tx + 32 * p;
        float bias0 = bg1[c0],     bias1 = bg1[c0 + 1];
        float w0    = Wg2[c0],     w1    = Wg2[c0 + 1];
        #pragma unroll
        for (int i = 0; i < 4; i++) {
            float f0, f1;
            unpack2(acc[i][p], f0, f1);
            float h0 = f0 + bias0; h0 = h0 > 0.f ? h0 : 0.f;
            float h1 = f1 + bias1; h1 = h1 > 0.f ? h1 : 0.f;
            part[i] = fmaf(h0, w0, part[i]);
            part[i] = fmaf(h1, w1, part[i]);
        }
    }
    #pragma unroll
    for (int i = 0; i < 4; i++) {
        #pragma unroll
        for (int off = 8; off > 0; off >>= 1)
            part[i] += __shfl_down_sync(0xffffffffu, part[i], off, 16);
    }
    if (tx == 0) {
        #pragma unroll
        for (int i = 0; i < 4; i++) {
            int row = brow + ty + 16 * i;
            if (row < B) atomicAdd(&graph_out[row], part[i]);
        }
    }
}

// ---------------------------------------------------------------------------
// Kernel 5: edge head
// ---------------------------------------------------------------------------
__global__ __launch_bounds__(256)
void edge_head(const int* __restrict__ edge_index,
               const int* __restrict__ rev,
               float* __restrict__ edge_out,
               int E)
{
    int k = blockIdx.x * blockDim.x + threadIdx.x;
    int half = E >> 1;
    if (k >= half) return;
    int e = 2 * k;
    if (!(e < rev[e])) e = 2 * k + 1;
    int a1 = edge_index[e];
    int a2 = edge_index[E + e];
    const float2* p1 = reinterpret_cast<const float2*>(g_atom_proj + (size_t)a1 * BF);
    const float2* p2 = reinterpret_cast<const float2*>(g_atom_proj + (size_t)a2 * BF);
    float2* o = reinterpret_cast<float2*>(edge_out + (size_t)k * BF);
    #pragma unroll
    for (int c = 0; c < BF / 2; c++) {
        float2 u = p1[c], v = p2[c];
        float2 r;
        r.x = 0.5f * (u.x + v.x);
        r.y = 0.5f * (u.y + v.y);
        o[c] = r;
    }
}

// ---------------------------------------------------------------------------
extern "C" void kernel_launch(void* const* d_in, const int* in_sizes, int n_in,
                              void* d_out, int out_size)
{
    const float* A    = (const float*)d_in[0];
    const float* Wn   = (const float*)d_in[1];
    const float* bn   = (const float*)d_in[2];
    const float* We   = (const float*)d_in[3];
    const float* be   = (const float*)d_in[4];
    const float* Wg1  = (const float*)d_in[5];
    const float* bg1  = (const float*)d_in[6];
    const float* Wg2  = (const float*)d_in[7];
    const float* bg2  = (const float*)d_in[8];
    const int* edge_index = (const int*)d_in[9];
    const int* rev        = (const int*)d_in[10];
    const int* batch      = (const int*)d_in[11];

    const int N = in_sizes[0] / H;
    const int E = in_sizes[9] / 2;
    const int half = E / 2;
    const int B = out_size - N * AF - half * BF;

    float* out = (float*)d_out;
    float* node_out  = out;
    float* edge_out  = out + (size_t)N * AF;
    float* graph_out = out + (size_t)N * AF + (size_t)half * BF;

    cudaFuncSetAttribute(gemm_mma, cudaFuncAttributeMaxDynamicSharedMemorySize, SMEM_DYN);

    static cudaStream_t s2 = nullptr;
    static cudaEvent_t ev_fork = nullptr, ev_join = nullptr;
    if (s2 == nullptr) {
        cudaStreamCreateWithFlags(&s2, cudaStreamNonBlocking);
        cudaEventCreateWithFlags(&ev_fork, cudaEventDisableTiming);
        cudaEventCreateWithFlags(&ev_join, cudaEventDisableTiming);
    }

    const long n8 = (long)N * H / 8;

    // main stream: pack -> convert -> [fork] -> gemm -> edge
    pack_w<<<(NPAD * H + 255) / 256, 256>>>(Wn, We);                       // 0
    convert_a<<<(int)((n8 + 255) / 256), 256>>>(A, n8);                    // 1

    // fork AFTER convert, BEFORE gemm: side stream depends only on g_A16
    cudaEventRecord(ev_fork, 0);
    cudaStreamWaitEvent(s2, ev_fork, 0);

    pool16<<<B, 128, 0, s2>>>(batch, N);                                   // 2 (s2)
    gemm_mma<<<(N + BM - 1) / BM, GT, SMEM_DYN>>>(bn, be, node_out, N);    // 3 (main, ncu slot)
    init_graph_out<<<(B + 255) / 256, 256, 0, s2>>>(graph_out, bg2, B);    // 4 (s2)
    graph_head<<<dim3((B + 63) / 64, H / 128), 256, 0, s2>>>(Wg1, bg1, Wg2, graph_out, B); // 5 (s2)
    edge_head<<<(half + 255) / 256, 256>>>(edge_index, rev, edge_out, E);  // 6 (main)

    cudaEventRecord(ev_join, s2);
    cudaStreamWaitEvent(0, ev_join, 0);
}

// round 15
// speedup vs baseline: 1.1127x; 1.1127x over previous
#include <cuda_runtime.h>
#include <cuda_fp16.h>
#include <cuda_bf16.h>
#include <cstdint>

// ---------------------------------------------------------------------------
// SSLPretrainModel v12 = v10 dataflow (fused pool+convert) + corrected fork:
//   graph_head depends only on pool_convert, runs on side stream under gemm.
//   D = A16 @ W16; rel_err 2.944e-4 << 1e-3 (identical arithmetic to v10).
// ---------------------------------------------------------------------------

#define H 512
#define AF 133
#define BF 14
#define NCOLS (AF + BF)      // 147
#define NPAD 160

#define MAX_N 204800
#define MAX_B 4608

__device__ float g_atom_proj[MAX_N * BF];
__device__ float g_graph_emb[MAX_B * H];
__device__ __align__(16) __half g_Wh[NPAD * H];           // W^T fp16 [160][512]
__device__ __align__(16) __half g_A16[(size_t)MAX_N * H]; // A fp16 [N][512]

// ---------------------------------------------------------------------------
// helpers
// ---------------------------------------------------------------------------
__device__ __forceinline__ uint32_t smem_u32(const void* p) {
    uint32_t a;
    asm("{ .reg .u64 t; cvta.to.shared.u64 t, %1; cvt.u32.u64 %0, t; }" : "=r"(a) : "l"(p));
    return a;
}

__device__ __forceinline__ uint32_t f16x2_pack(float lo_elem, float hi_elem) {
    uint32_t r;
    asm("cvt.rn.f16x2.f32 %0, %1, %2;" : "=r"(r) : "f"(hi_elem), "f"(lo_elem));
    return r;
}

__device__ __forceinline__ void mma16816(float& d0, float& d1, float& d2, float& d3,
                                         uint32_t a0, uint32_t a1, uint32_t a2, uint32_t a3,
                                         uint32_t b0, uint32_t b1) {
    asm volatile(
        "mma.sync.aligned.m16n8k16.row.col.f32.f16.f16.f32 "
        "{%0,%1,%2,%3}, {%4,%5,%6,%7}, {%8,%9}, {%0,%1,%2,%3};"
        : "+f"(d0), "+f"(d1), "+f"(d2), "+f"(d3)
        : "r"(a0), "r"(a1), "r"(a2), "r"(a3), "r"(b0), "r"(b1));
}

__device__ __forceinline__ void ldmx4(uint32_t& r0, uint32_t& r1, uint32_t& r2,
                                      uint32_t& r3, uint32_t addr) {
    asm volatile("ldmatrix.sync.aligned.m8n8.x4.shared.b16 {%0,%1,%2,%3}, [%4];"
                 : "=r"(r0), "=r"(r1), "=r"(r2), "=r"(r3) : "r"(addr));
}
__device__ __forceinline__ void ldmx2(uint32_t& r0, uint32_t& r1, uint32_t addr) {
    asm volatile("ldmatrix.sync.aligned.m8n8.x2.shared.b16 {%0,%1}, [%2];"
                 : "=r"(r0), "=r"(r1) : "r"(addr));
}

#define CP_ASYNC16(saddr, gptr) \
    asm volatile("cp.async.cg.shared.global [%0], [%1], 16;" :: "r"(saddr), "l"(gptr))
#define CP_COMMIT() asm volatile("cp.async.commit_group;" ::: "memory")
#define CP_WAIT0()  asm volatile("cp.async.wait_group 0;" ::: "memory")

// ---------------------------------------------------------------------------
// Kernel 0: pack fused W^T into fp16.
// ---------------------------------------------------------------------------
__global__ void pack_w(const float* __restrict__ Wn,
                       const float* __restrict__ We)
{
    int idx = blockIdx.x * 256 + threadIdx.x;
    if (idx >= NPAD * H) return;
    int n = idx >> 9;
    int k = idx & 511;
    float v = 0.f;
    if (n < AF)         v = Wn[k * AF + n];
    else if (n < NCOLS) v = We[k * BF + (n - AF)];
    g_Wh[idx] = __float2half_rn(v);
}

// ---------------------------------------------------------------------------
// Kernel 1: segment pool FUSED with A->fp16 conversion (reads A exactly once).
// ---------------------------------------------------------------------------
__global__ __launch_bounds__(128)
void pool_convert(const float* __restrict__ A,
                  const int* __restrict__ batch,
                  int N)
{
    const int g = blockIdx.x;

    int lo = 0, hi = N;
    while (lo < hi) { int m = (lo + hi) >> 1; if (batch[m] < g) lo = m + 1; else hi = m; }
    const int start = lo;
    hi = N;
    while (lo < hi) { int m = (lo + hi) >> 1; if (batch[m] < g + 1) lo = m + 1; else hi = m; }
    const int end = lo;

    const int t = threadIdx.x;
    float4 s0 = make_float4(0.f, 0.f, 0.f, 0.f);
    float4 s1 = make_float4(0.f, 0.f, 0.f, 0.f);
    int i = start;
    for (; i + 1 < end; i += 2) {
        float4 v0 = reinterpret_cast<const float4*>(A + (size_t)i * H)[t];
        float4 v1 = reinterpret_cast<const float4*>(A + (size_t)(i + 1) * H)[t];
        s0.x += v0.x; s0.y += v0.y; s0.z += v0.z; s0.w += v0.w;
        s1.x += v1.x; s1.y += v1.y; s1.z += v1.z; s1.w += v1.w;
        uint2 p0 = make_uint2(f16x2_pack(v0.x, v0.y), f16x2_pack(v0.z, v0.w));
        uint2 p1 = make_uint2(f16x2_pack(v1.x, v1.y), f16x2_pack(v1.z, v1.w));
        reinterpret_cast<uint2*>(g_A16 + (size_t)i * H)[t] = p0;
        reinterpret_cast<uint2*>(g_A16 + (size_t)(i + 1) * H)[t] = p1;
    }
    if (i < end) {
        float4 v0 = reinterpret_cast<const float4*>(A + (size_t)i * H)[t];
        s0.x += v0.x; s0.y += v0.y; s0.z += v0.z; s0.w += v0.w;
        uint2 p0 = make_uint2(f16x2_pack(v0.x, v0.y), f16x2_pack(v0.z, v0.w));
        reinterpret_cast<uint2*>(g_A16 + (size_t)i * H)[t] = p0;
    }
    s0.x += s1.x; s0.y += s1.y; s0.z += s1.z; s0.w += s1.w;
    reinterpret_cast<float4*>(g_graph_emb + (size_t)g * H)[t] = s0;
}

// ---------------------------------------------------------------------------
// Kernel 2: HMMA GEMM  C[N,147] = A16[N,512] @ Wf (+bias epilogue)
// CTA 128x160, 256 threads, 2 CTAs/SM. Warp grid 2(m) x 4(n); warp tile 64x40.
// BK=64; all operands via cp.async.
// ---------------------------------------------------------------------------
#define BKC 64
#define PITCH 144
#define BM 128
#define A_TILE (BM * PITCH)                // 18432
#define B_TILE (160 * PITCH)               // 23040
#define OFF_A 0
#define OFF_B (A_TILE)
#define BUFB (A_TILE + B_TILE)             // 41472
#define SMEM_DYN (2 * BUFB)                // 82944
#define GT 256

__global__ __launch_bounds__(GT, 2)
void gemm_mma(const float* __restrict__ bn,
              const float* __restrict__ be,
              float* __restrict__ node_out,
              int N)
{
    extern __shared__ char dyn[];
    __shared__ float s_bias[NPAD];

    const int tid = threadIdx.x;
    const int wid = tid >> 5;
    const int lid = tid & 31;
    const int block_row = blockIdx.x * BM;
    const uint32_t sbase = smem_u32(dyn);

    if (tid < NPAD) {
        float b = 0.f;
        if (tid < AF) b = bn[tid];
        else if (tid < NCOLS) b = be[tid - AF];
        s_bias[tid] = b;
    }

    const __half* asrc[4];
    uint32_t asmem[4];
    bool aact[4];
    #pragma unroll
    for (int i = 0; i < 4; i++) {
        int idx = tid + i * GT;
        int r  = idx >> 3;
        int j  = idx & 7;
        aact[i]  = (block_row + r < N);
        asrc[i]  = g_A16 + (size_t)(block_row + r) * H + j * 8;
        asmem[i] = (uint32_t)(OFF_A + r * PITCH + j * 16);
    }
    const __half* bsrc[5];
    uint32_t bsmem[5];
    #pragma unroll
    for (int i = 0; i < 5; i++) {
        int idx = tid + i * GT;
        int r  = idx >> 3;
        int j  = idx & 7;
        bsrc[i]  = g_Wh + (size_t)r * H + j * 8;
        bsmem[i] = (uint32_t)(OFF_B + r * PITCH + j * 16);
    }

    auto cpAB = [&](int c, int buf) {
        const uint32_t bb = sbase + buf * BUFB;
        #pragma unroll
        for (int i = 0; i < 4; i++)
            if (aact[i]) CP_ASYNC16(bb + asmem[i], asrc[i] + c * BKC);
        #pragma unroll
        for (int i = 0; i < 5; i++)
            CP_ASYNC16(bb + bsmem[i], bsrc[i] + c * BKC);
        CP_COMMIT();
    };

    float acc[4][5][4];
    #pragma unroll
    for (int mt = 0; mt < 4; mt++)
        #pragma unroll
        for (int nt = 0; nt < 5; nt++)
            #pragma unroll
            for (int q = 0; q < 4; q++) acc[mt][nt][q] = 0.f;

    const int wm = wid & 1;
    const int wn = wid >> 1;
    const int g  = lid >> 2;
    const int t  = lid & 3;
    const int lid16 = lid & 15;

    const uint32_t a_lm = (uint32_t)((wm * 64 + lid16) * PITCH + (lid >> 4) * 16);
    uint32_t b_lm4[2];
    #pragma unroll
    for (int p = 0; p < 2; p++)
        b_lm4[p] = (uint32_t)((wn * 40 + p * 16 + (lid & 7) + ((lid >> 4) & 1) * 8) * PITCH
                              + ((lid >> 3) & 1) * 16);
    const uint32_t b_lm2 = (uint32_t)((wn * 40 + 32 + (lid16 & 7)) * PITCH
                                      + ((lid16 >> 3) & 1) * 16);

    cpAB(0, 0);
    CP_WAIT0();
    __syncthreads();

    const int NCH = H / BKC;   // 8
    for (int c = 0; c < NCH; c++) {
        const int buf = c & 1;
        const uint32_t base = sbase + buf * BUFB;

        if (c + 1 < NCH) cpAB(c + 1, buf ^ 1);

        #pragma unroll
        for (int ks = 0; ks < 4; ks++) {
            const uint32_t kb = ks * 32;
            uint32_t fa[4][4];
            #pragma unroll
            for (int mt = 0; mt < 4; mt++)
                ldmx4(fa[mt][0], fa[mt][1], fa[mt][2], fa[mt][3],
                      base + OFF_A + a_lm + mt * 16 * PITCH + kb);

            uint32_t bh[10];
            ldmx4(bh[0], bh[1], bh[2], bh[3], base + OFF_B + b_lm4[0] + kb);
            ldmx4(bh[4], bh[5], bh[6], bh[7], base + OFF_B + b_lm4[1] + kb);
            ldmx2(bh[8], bh[9],              base + OFF_B + b_lm2 + kb);

            #pragma unroll
            for (int nt = 0; nt < 5; nt++) {
                uint32_t h0 = bh[2*nt], h1 = bh[2*nt+1];
                #pragma unroll
                for (int mt = 0; mt < 4; mt++) {
                    float* d = acc[mt][nt];
                    mma16816(d[0],d[1],d[2],d[3],
                             fa[mt][0],fa[mt][1],fa[mt][2],fa[mt][3], h0, h1);
                }
            }
        }

        if (c + 1 < NCH) {
            CP_WAIT0();
            __syncthreads();
        }
    }

    #pragma unroll
    for (int mt = 0; mt < 4; mt++) {
        #pragma unroll
        for (int half = 0; half < 2; half++) {
            int row = block_row + wm * 64 + mt * 16 + g + half * 8;
            if (row >= N) continue;
            float* nrow = node_out + (size_t)row * AF;
            float* prow = g_atom_proj + (size_t)row * BF;
            #pragma unroll
            for (int nt = 0; nt < 5; nt++) {
                int col = wn * 40 + nt * 8 + 2 * t;
                float v0 = acc[mt][nt][2 * half + 0] + s_bias[col];
                float v1 = acc[mt][nt][2 * half + 1] + s_bias[col + 1];
                if (col < AF)          nrow[col] = v0;
                else if (col < NCOLS)  prow[col - AF] = v0;
                if (col + 1 < AF)          nrow[col + 1] = v1;
                else if (col + 1 < NCOLS)  prow[col + 1 - AF] = v1;
            }
        }
    }
}

// ---------------------------------------------------------------------------
// Kernel 3a: init graph output with b_g2
// ---------------------------------------------------------------------------
__global__ void init_graph_out(float* __restrict__ graph_out,
                               const float* __restrict__ bg2, int B)
{
    int g = blockIdx.x * blockDim.x + threadIdx.x;
    if (g < B) graph_out[g] = bg2[0];
}

// ---------------------------------------------------------------------------
// Kernel 3b: graph head (FFMA2)
// ---------------------------------------------------------------------------
__device__ __forceinline__ unsigned long long pack_dup(float a) {
    unsigned long long r;
    unsigned int ab = __float_as_uint(a);
    asm("mov.b64 %0, {%1, %1};" : "=l"(r) : "r"(ab));
    return r;
}
__device__ __forceinline__ void fma2(unsigned long long& d,
                                     unsigned long long a,
                                     unsigned long long b) {
    asm("fma.rn.f32x2 %0, %1, %2, %0;" : "+l"(d) : "l"(a), "l"(b));
}
__device__ __forceinline__ void unpack2(unsigned long long v, float& lo, float& hi) {
    unsigned int l, h;
    asm("mov.b64 {%0, %1}, %2;" : "=r"(l), "=r"(h) : "l"(v));
    lo = __uint_as_float(l);
    hi = __uint_as_float(h);
}

__global__ __launch_bounds__(256)
void graph_head(const float* __restrict__ Wg1,
                const float* __restrict__ bg1,
                const float* __restrict__ Wg2,
                float* __restrict__ graph_out,
                int B)
{
    __shared__ float Es[32][65];
    __shared__ float Ws2[32][132];

    const int brow = blockIdx.x * 64;
    const int bcol = blockIdx.y * 128;
    const int tid = threadIdx.x;
    const int tx = tid & 15;
    const int ty = tid >> 4;

    unsigned long long acc[4][4];
    #pragma unroll
    for (int i = 0; i < 4; i++)
        #pragma unroll
        for (int p = 0; p < 4; p++) acc[i][p] = 0ull;

    for (int k0 = 0; k0 < H; k0 += 32) {
        #pragma unroll
        for (int it = 0; it < 2; it++) {
            int i = tid + it * 256;
            int r  = i >> 3;
            int c4 = i & 7;
            int row = brow + r;
            float4 v = make_float4(0.f, 0.f, 0.f, 0.f);
            if (row < B)
                v = reinterpret_cast<const float4*>(g_graph_emb + (size_t)row * H + k0)[c4];
            Es[c4 * 4 + 0][r] = v.x;
            Es[c4 * 4 + 1][r] = v.y;
            Es[c4 * 4 + 2][r] = v.z;
            Es[c4 * 4 + 3][r] = v.w;
        }
        #pragma unroll
        for (int it = 0; it < 4; it++) {
            int i = tid + it * 256;
            int kk = i >> 5;
            int c4 = i & 31;
            float4 v = reinterpret_cast<const float4*>(Wg1 + (size_t)(k0 + kk) * H + bcol)[c4];
            *reinterpret_cast<float4*>(&Ws2[kk][c4 * 4]) = v;
        }
        __syncthreads();

        #pragma unroll 8
        for (int kk = 0; kk < 32; kk++) {
            unsigned long long b2[4];
            #pragma unroll
            for (int p = 0; p < 4; p++)
                b2[p] = *reinterpret_cast<const unsigned long long*>(&Ws2[kk][2 * tx + 32 * p]);
            #pragma unroll
            for (int i = 0; i < 4; i++) {
                unsigned long long a2 = pack_dup(Es[kk][ty + 16 * i]);
                #pragma unroll
                for (int p = 0; p < 4; p++)
                    fma2(acc[i][p], a2, b2[p]);
            }
        }
        __syncthreads();
    }

    float part[4] = {0.f, 0.f, 0.f, 0.f};
    #pragma unroll
    for (int p = 0; p < 4; p++) {
        int c0 = bcol + 2 * tx + 32 * p;
        float bias0 = bg1[c0],     bias1 = bg1[c0 + 1];
        float w0    = Wg2[c0],     w1    = Wg2[c0 + 1];
        #pragma unroll
        for (int i = 0; i < 4; i++) {
            float f0, f1;
            unpack2(acc[i][p], f0, f1);
            float h0 = f0 + bias0; h0 = h0 > 0.f ? h0 : 0.f;
            float h1 = f1 + bias1; h1 = h1 > 0.f ? h1 : 0.f;
            part[i] = fmaf(h0, w0, part[i]);
            part[i] = fmaf(h1, w1, part[i]);
        }
    }
    #pragma unroll
    for (int i = 0; i < 4; i++) {
        #pragma unroll
        for (int off = 8; off > 0; off >>= 1)
            part[i] += __shfl_down_sync(0xffffffffu, part[i], off, 16);
    }
    if (tx == 0) {
        #pragma unroll
        for (int i = 0; i < 4; i++) {
            int row = brow + ty + 16 * i;
            if (row < B) atomicAdd(&graph_out[row], part[i]);
        }
    }
}

// ---------------------------------------------------------------------------
// Kernel 4: edge head
// ---------------------------------------------------------------------------
__global__ __launch_bounds__(256)
void edge_head(const int* __restrict__ edge_index,
               const int* __restrict__ rev,
               float* __restrict__ edge_out,
               int E)
{
    int k = blockIdx.x * blockDim.x + threadIdx.x;
    int half = E >> 1;
    if (k >= half) return;
    int e = 2 * k;
    if (!(e < rev[e])) e = 2 * k + 1;
    int a1 = edge_index[e];
    int a2 = edge_index[E + e];
    const float2* p1 = reinterpret_cast<const float2*>(g_atom_proj + (size_t)a1 * BF);
    const float2* p2 = reinterpret_cast<const float2*>(g_atom_proj + (size_t)a2 * BF);
    float2* o = reinterpret_cast<float2*>(edge_out + (size_t)k * BF);
    #pragma unroll
    for (int c = 0; c < BF / 2; c++) {
        float2 u = p1[c], v = p2[c];
        float2 r;
        r.x = 0.5f * (u.x + v.x);
        r.y = 0.5f * (u.y + v.y);
        o[c] = r;
    }
}

// ---------------------------------------------------------------------------
extern "C" void kernel_launch(void* const* d_in, const int* in_sizes, int n_in,
                              void* d_out, int out_size)
{
    const float* A    = (const float*)d_in[0];
    const float* Wn   = (const float*)d_in[1];
    const float* bn   = (const float*)d_in[2];
    const float* We   = (const float*)d_in[3];
    const float* be   = (const float*)d_in[4];
    const float* Wg1  = (const float*)d_in[5];
    const float* bg1  = (const float*)d_in[6];
    const float* Wg2  = (const float*)d_in[7];
    const float* bg2  = (const float*)d_in[8];
    const int* edge_index = (const int*)d_in[9];
    const int* rev        = (const int*)d_in[10];
    const int* batch      = (const int*)d_in[11];

    const int N = in_sizes[0] / H;
    const int E = in_sizes[9] / 2;
    const int half = E / 2;
    const int B = out_size - N * AF - half * BF;

    float* out = (float*)d_out;
    float* node_out  = out;
    float* edge_out  = out + (size_t)N * AF;
    float* graph_out = out + (size_t)N * AF + (size_t)half * BF;

    cudaFuncSetAttribute(gemm_mma, cudaFuncAttributeMaxDynamicSharedMemorySize, SMEM_DYN);

    static cudaStream_t s2 = nullptr;
    static cudaEvent_t ev_fork = nullptr, ev_join = nullptr;
    if (s2 == nullptr) {
        cudaStreamCreateWithFlags(&s2, cudaStreamNonBlocking);
        cudaEventCreateWithFlags(&ev_fork, cudaEventDisableTiming);
        cudaEventCreateWithFlags(&ev_join, cudaEventDisableTiming);
    }

    // main: pack -> pool_convert -> [fork] -> gemm -> edge
    pack_w<<<(NPAD * H + 255) / 256, 256>>>(Wn, We);                       // 0
    pool_convert<<<B, 128>>>(A, batch, N);                                 // 1

    // fork recorded AFTER pool_convert, BEFORE gemm: side stream depends
    // only on g_graph_emb (and graph_out), so head can overlap the gemm.
    cudaEventRecord(ev_fork, 0);
    cudaStreamWaitEvent(s2, ev_fork, 0);

    init_graph_out<<<(B + 255) / 256, 256, 0, s2>>>(graph_out, bg2, B);    // 2 (s2)
    gemm_mma<<<(N + BM - 1) / BM, GT, SMEM_DYN>>>(bn, be, node_out, N);    // 3 (main, ncu slot)
    graph_head<<<dim3((B + 63) / 64, H / 128), 256, 0, s2>>>(Wg1, bg1, Wg2, graph_out, B); // 4 (s2)
    edge_head<<<(half + 255) / 256, 256>>>(edge_index, rev, edge_out, E);  // 5 (main)

    cudaEventRecord(ev_join, s2);
    cudaStreamWaitEvent(0, ev_join, 0);
}

// round 16
// speedup vs baseline: 1.3405x; 1.2047x over previous
#include <cuda_runtime.h>
#include <cuda_fp16.h>
#include <cuda_bf16.h>
#include <cstdint>

// ---------------------------------------------------------------------------
// SSLPretrainModel v13 = v10 dataflow + HMMA graph head:
//   pool_convert -> g_A16 + g_graph_emb(fp32) + g_emb16(fp16)
//   gemm_mma (node+edge proj, fp16 HMMA)
//   graph_head_mma (fp16 HMMA, relu + Wg2 dot fused, atomic row partials)
// ---------------------------------------------------------------------------

#define H 512
#define AF 133
#define BF 14
#define NCOLS (AF + BF)      // 147
#define NPAD 160

#define MAX_N 204800
#define MAX_B 4608

__device__ float g_atom_proj[MAX_N * BF];
__device__ float g_graph_emb[MAX_B * H];
__device__ __align__(16) __half g_Wh[NPAD * H];            // W^T fp16 [160][512]
__device__ __align__(16) __half g_Wg1h[H * H];             // Wg1^T fp16 [512][512]
__device__ __align__(16) __half g_A16[(size_t)MAX_N * H];  // A fp16 [N][512]
__device__ __align__(16) __half g_emb16[MAX_B * H];        // emb fp16 [B][512]

// ---------------------------------------------------------------------------
// helpers
// ---------------------------------------------------------------------------
__device__ __forceinline__ uint32_t smem_u32(const void* p) {
    uint32_t a;
    asm("{ .reg .u64 t; cvta.to.shared.u64 t, %1; cvt.u32.u64 %0, t; }" : "=r"(a) : "l"(p));
    return a;
}

__device__ __forceinline__ uint32_t f16x2_pack(float lo_elem, float hi_elem) {
    uint32_t r;
    asm("cvt.rn.f16x2.f32 %0, %1, %2;" : "=r"(r) : "f"(hi_elem), "f"(lo_elem));
    return r;
}

__device__ __forceinline__ void mma16816(float& d0, float& d1, float& d2, float& d3,
                                         uint32_t a0, uint32_t a1, uint32_t a2, uint32_t a3,
                                         uint32_t b0, uint32_t b1) {
    asm volatile(
        "mma.sync.aligned.m16n8k16.row.col.f32.f16.f16.f32 "
        "{%0,%1,%2,%3}, {%4,%5,%6,%7}, {%8,%9}, {%0,%1,%2,%3};"
        : "+f"(d0), "+f"(d1), "+f"(d2), "+f"(d3)
        : "r"(a0), "r"(a1), "r"(a2), "r"(a3), "r"(b0), "r"(b1));
}

__device__ __forceinline__ void ldmx4(uint32_t& r0, uint32_t& r1, uint32_t& r2,
                                      uint32_t& r3, uint32_t addr) {
    asm volatile("ldmatrix.sync.aligned.m8n8.x4.shared.b16 {%0,%1,%2,%3}, [%4];"
                 : "=r"(r0), "=r"(r1), "=r"(r2), "=r"(r3) : "r"(addr));
}
__device__ __forceinline__ void ldmx2(uint32_t& r0, uint32_t& r1, uint32_t addr) {
    asm volatile("ldmatrix.sync.aligned.m8n8.x2.shared.b16 {%0,%1}, [%2];"
                 : "=r"(r0), "=r"(r1) : "r"(addr));
}

#define CP_ASYNC16(saddr, gptr) \
    asm volatile("cp.async.cg.shared.global [%0], [%1], 16;" :: "r"(saddr), "l"(gptr))
#define CP_COMMIT() asm volatile("cp.async.commit_group;" ::: "memory")
#define CP_WAIT0()  asm volatile("cp.async.wait_group 0;" ::: "memory")

// ---------------------------------------------------------------------------
// Kernel 0: pack ALL weights to fp16 (fused W^T and Wg1^T) in one launch.
// ---------------------------------------------------------------------------
#define PACK_TOTAL (NPAD * H + H * H)   // 81920 + 262144 = 344064

__global__ void pack_all(const float* __restrict__ Wn,
                         const float* __restrict__ We,
                         const float* __restrict__ Wg1)
{
    int idx = blockIdx.x * 256 + threadIdx.x;
    if (idx >= PACK_TOTAL) return;
    if (idx < NPAD * H) {
        int n = idx >> 9;
        int k = idx & 511;
        float v = 0.f;
        if (n < AF)         v = Wn[k * AF + n];
        else if (n < NCOLS) v = We[k * BF + (n - AF)];
        g_Wh[idx] = __float2half_rn(v);
    } else {
        int j = idx - NPAD * H;
        int n = j >> 9;
        int k = j & 511;
        g_Wg1h[j] = __float2half_rn(Wg1[k * H + n]);
    }
}

// ---------------------------------------------------------------------------
// Kernel 1: segment pool FUSED with A->fp16 conversion; also emits emb fp16.
// ---------------------------------------------------------------------------
__global__ __launch_bounds__(128)
void pool_convert(const float* __restrict__ A,
                  const int* __restrict__ batch,
                  int N)
{
    const int g = blockIdx.x;

    int lo = 0, hi = N;
    while (lo < hi) { int m = (lo + hi) >> 1; if (batch[m] < g) lo = m + 1; else hi = m; }
    const int start = lo;
    hi = N;
    while (lo < hi) { int m = (lo + hi) >> 1; if (batch[m] < g + 1) lo = m + 1; else hi = m; }
    const int end = lo;

    const int t = threadIdx.x;
    float4 s0 = make_float4(0.f, 0.f, 0.f, 0.f);
    float4 s1 = make_float4(0.f, 0.f, 0.f, 0.f);
    int i = start;
    for (; i + 1 < end; i += 2) {
        float4 v0 = reinterpret_cast<const float4*>(A + (size_t)i * H)[t];
        float4 v1 = reinterpret_cast<const float4*>(A + (size_t)(i + 1) * H)[t];
        s0.x += v0.x; s0.y += v0.y; s0.z += v0.z; s0.w += v0.w;
        s1.x += v1.x; s1.y += v1.y; s1.z += v1.z; s1.w += v1.w;
        uint2 p0 = make_uint2(f16x2_pack(v0.x, v0.y), f16x2_pack(v0.z, v0.w));
        uint2 p1 = make_uint2(f16x2_pack(v1.x, v1.y), f16x2_pack(v1.z, v1.w));
        reinterpret_cast<uint2*>(g_A16 + (size_t)i * H)[t] = p0;
        reinterpret_cast<uint2*>(g_A16 + (size_t)(i + 1) * H)[t] = p1;
    }
    if (i < end) {
        float4 v0 = reinterpret_cast<const float4*>(A + (size_t)i * H)[t];
        s0.x += v0.x; s0.y += v0.y; s0.z += v0.z; s0.w += v0.w;
        uint2 p0 = make_uint2(f16x2_pack(v0.x, v0.y), f16x2_pack(v0.z, v0.w));
        reinterpret_cast<uint2*>(g_A16 + (size_t)i * H)[t] = p0;
    }
    s0.x += s1.x; s0.y += s1.y; s0.z += s1.z; s0.w += s1.w;
    reinterpret_cast<float4*>(g_graph_emb + (size_t)g * H)[t] = s0;
    uint2 e = make_uint2(f16x2_pack(s0.x, s0.y), f16x2_pack(s0.z, s0.w));
    reinterpret_cast<uint2*>(g_emb16 + (size_t)g * H)[t] = e;
}

// ---------------------------------------------------------------------------
// Kernel 2: HMMA GEMM  C[N,147] = A16[N,512] @ Wf (+bias epilogue)
// CTA 128x160, 256 threads, 2 CTAs/SM. Warp grid 2(m) x 4(n); warp tile 64x40.
// ---------------------------------------------------------------------------
#define BKC 64
#define PITCH 144
#define BM 128
#define A_TILE (BM * PITCH)                // 18432
#define B_TILE (160 * PITCH)               // 23040
#define OFF_A 0
#define OFF_B (A_TILE)
#define BUFB (A_TILE + B_TILE)             // 41472
#define SMEM_DYN (2 * BUFB)                // 82944
#define GT 256

__global__ __launch_bounds__(GT, 2)
void gemm_mma(const float* __restrict__ bn,
              const float* __restrict__ be,
              float* __restrict__ node_out,
              int N)
{
    extern __shared__ char dyn[];
    __shared__ float s_bias[NPAD];

    const int tid = threadIdx.x;
    const int wid = tid >> 5;
    const int lid = tid & 31;
    const int block_row = blockIdx.x * BM;
    const uint32_t sbase = smem_u32(dyn);

    if (tid < NPAD) {
        float b = 0.f;
        if (tid < AF) b = bn[tid];
        else if (tid < NCOLS) b = be[tid - AF];
        s_bias[tid] = b;
    }

    const __half* asrc[4];
    uint32_t asmem[4];
    bool aact[4];
    #pragma unroll
    for (int i = 0; i < 4; i++) {
        int idx = tid + i * GT;
        int r  = idx >> 3;
        int j  = idx & 7;
        aact[i]  = (block_row + r < N);
        asrc[i]  = g_A16 + (size_t)(block_row + r) * H + j * 8;
        asmem[i] = (uint32_t)(OFF_A + r * PITCH + j * 16);
    }
    const __half* bsrc[5];
    uint32_t bsmem[5];
    #pragma unroll
    for (int i = 0; i < 5; i++) {
        int idx = tid + i * GT;
        int r  = idx >> 3;
        int j  = idx & 7;
        bsrc[i]  = g_Wh + (size_t)r * H + j * 8;
        bsmem[i] = (uint32_t)(OFF_B + r * PITCH + j * 16);
    }

    auto cpAB = [&](int c, int buf) {
        const uint32_t bb = sbase + buf * BUFB;
        #pragma unroll
        for (int i = 0; i < 4; i++)
            if (aact[i]) CP_ASYNC16(bb + asmem[i], asrc[i] + c * BKC);
        #pragma unroll
        for (int i = 0; i < 5; i++)
            CP_ASYNC16(bb + bsmem[i], bsrc[i] + c * BKC);
        CP_COMMIT();
    };

    float acc[4][5][4];
    #pragma unroll
    for (int mt = 0; mt < 4; mt++)
        #pragma unroll
        for (int nt = 0; nt < 5; nt++)
            #pragma unroll
            for (int q = 0; q < 4; q++) acc[mt][nt][q] = 0.f;

    const int wm = wid & 1;
    const int wn = wid >> 1;
    const int g  = lid >> 2;
    const int t  = lid & 3;
    const int lid16 = lid & 15;

    const uint32_t a_lm = (uint32_t)((wm * 64 + lid16) * PITCH + (lid >> 4) * 16);
    uint32_t b_lm4[2];
    #pragma unroll
    for (int p = 0; p < 2; p++)
        b_lm4[p] = (uint32_t)((wn * 40 + p * 16 + (lid & 7) + ((lid >> 4) & 1) * 8) * PITCH
                              + ((lid >> 3) & 1) * 16);
    const uint32_t b_lm2 = (uint32_t)((wn * 40 + 32 + (lid16 & 7)) * PITCH
                                      + ((lid16 >> 3) & 1) * 16);

    cpAB(0, 0);
    CP_WAIT0();
    __syncthreads();

    const int NCH = H / BKC;   // 8
    for (int c = 0; c < NCH; c++) {
        const int buf = c & 1;
        const uint32_t base = sbase + buf * BUFB;

        if (c + 1 < NCH) cpAB(c + 1, buf ^ 1);

        #pragma unroll
        for (int ks = 0; ks < 4; ks++) {
            const uint32_t kb = ks * 32;
            uint32_t fa[4][4];
            #pragma unroll
            for (int mt = 0; mt < 4; mt++)
                ldmx4(fa[mt][0], fa[mt][1], fa[mt][2], fa[mt][3],
                      base + OFF_A + a_lm + mt * 16 * PITCH + kb);

            uint32_t bh[10];
            ldmx4(bh[0], bh[1], bh[2], bh[3], base + OFF_B + b_lm4[0] + kb);
            ldmx4(bh[4], bh[5], bh[6], bh[7], base + OFF_B + b_lm4[1] + kb);
            ldmx2(bh[8], bh[9],              base + OFF_B + b_lm2 + kb);

            #pragma unroll
            for (int nt = 0; nt < 5; nt++) {
                uint32_t h0 = bh[2*nt], h1 = bh[2*nt+1];
                #pragma unroll
                for (int mt = 0; mt < 4; mt++) {
                    float* d = acc[mt][nt];
                    mma16816(d[0],d[1],d[2],d[3],
                             fa[mt][0],fa[mt][1],fa[mt][2],fa[mt][3], h0, h1);
                }
            }
        }

        if (c + 1 < NCH) {
            CP_WAIT0();
            __syncthreads();
        }
    }

    #pragma unroll
    for (int mt = 0; mt < 4; mt++) {
        #pragma unroll
        for (int half = 0; half < 2; half++) {
            int row = block_row + wm * 64 + mt * 16 + g + half * 8;
            if (row >= N) continue;
            float* nrow = node_out + (size_t)row * AF;
            float* prow = g_atom_proj + (size_t)row * BF;
            #pragma unroll
            for (int nt = 0; nt < 5; nt++) {
                int col = wn * 40 + nt * 8 + 2 * t;
                float v0 = acc[mt][nt][2 * half + 0] + s_bias[col];
                float v1 = acc[mt][nt][2 * half + 1] + s_bias[col + 1];
                if (col < AF)          nrow[col] = v0;
                else if (col < NCOLS)  prow[col - AF] = v0;
                if (col + 1 < AF)          nrow[col + 1] = v1;
                else if (col + 1 < NCOLS)  prow[col + 1 - AF] = v1;
            }
        }
    }
}

// ---------------------------------------------------------------------------
// Kernel 3a: init graph output with b_g2
// ---------------------------------------------------------------------------
__global__ void init_graph_out(float* __restrict__ graph_out,
                               const float* __restrict__ bg2, int B)
{
    int g = blockIdx.x * blockDim.x + threadIdx.x;
    if (g < B) graph_out[g] = bg2[0];
}

// ---------------------------------------------------------------------------
// Kernel 3b: graph head on HMMA.
// CTA 128 rows x 128 cols, grid (B/128, 4). K=512, BKC=64, double buffered.
// Epilogue: relu(acc + bg1) * Wg2, quad-reduce, atomicAdd row partial.
// ---------------------------------------------------------------------------
#define GH_A_TILE (128 * PITCH)            // 18432
#define GH_B_TILE (128 * PITCH)            // 18432
#define GH_OFF_A 0
#define GH_OFF_B (GH_A_TILE)
#define GH_BUFB (GH_A_TILE + GH_B_TILE)    // 36864
#define GH_SMEM (2 * GH_BUFB)              // 73728

__global__ __launch_bounds__(256, 2)
void graph_head_mma(const float* __restrict__ bg1,
                    const float* __restrict__ Wg2,
                    float* __restrict__ graph_out,
                    int B)
{
    extern __shared__ char dyn[];
    __shared__ float s_bg1[128];
    __shared__ float s_wg2[128];

    const int tid = threadIdx.x;
    const int wid = tid >> 5;
    const int lid = tid & 31;
    const int brow = blockIdx.x * 128;
    const int bcol = blockIdx.y * 128;
    const uint32_t sbase = smem_u32(dyn);

    if (tid < 128) {
        s_bg1[tid] = bg1[bcol + tid];
        s_wg2[tid] = Wg2[bcol + tid];
    }

    // A (emb16): 128 rows x 8 x 16B -> 4 per thread
    const __half* asrc[4];
    uint32_t asmem[4];
    bool aact[4];
    #pragma unroll
    for (int i = 0; i < 4; i++) {
        int idx = tid + i * 256;
        int r  = idx >> 3;
        int j  = idx & 7;
        aact[i]  = (brow + r < B);
        asrc[i]  = g_emb16 + (size_t)(brow + r) * H + j * 8;
        asmem[i] = (uint32_t)(GH_OFF_A + r * PITCH + j * 16);
    }
    // B (Wg1^T rows bcol..bcol+127): 4 per thread
    const __half* bsrc[4];
    uint32_t bsmem[4];
    #pragma unroll
    for (int i = 0; i < 4; i++) {
        int idx = tid + i * 256;
        int r  = idx >> 3;
        int j  = idx & 7;
        bsrc[i]  = g_Wg1h + (size_t)(bcol + r) * H + j * 8;
        bsmem[i] = (uint32_t)(GH_OFF_B + r * PITCH + j * 16);
    }

    auto cpAB = [&](int c, int buf) {
        const uint32_t bb = sbase + buf * GH_BUFB;
        #pragma unroll
        for (int i = 0; i < 4; i++)
            if (aact[i]) CP_ASYNC16(bb + asmem[i], asrc[i] + c * BKC);
        #pragma unroll
        for (int i = 0; i < 4; i++)
            CP_ASYNC16(bb + bsmem[i], bsrc[i] + c * BKC);
        CP_COMMIT();
    };

    float acc[4][4][4];
    #pragma unroll
    for (int mt = 0; mt < 4; mt++)
        #pragma unroll
        for (int nt = 0; nt < 4; nt++)
            #pragma unroll
            for (int q = 0; q < 4; q++) acc[mt][nt][q] = 0.f;

    const int wm = wid & 1;          // 0..1 (64-row halves)
    const int wn = wid >> 1;         // 0..3 (32-col slices)
    const int g  = lid >> 2;
    const int t  = lid & 3;
    const int lid16 = lid & 15;

    const uint32_t a_lm = (uint32_t)((wm * 64 + lid16) * PITCH + (lid >> 4) * 16);
    uint32_t b_lm4[2];
    #pragma unroll
    for (int p = 0; p < 2; p++)
        b_lm4[p] = (uint32_t)((wn * 32 + p * 16 + (lid & 7) + ((lid >> 4) & 1) * 8) * PITCH
                              + ((lid >> 3) & 1) * 16);

    cpAB(0, 0);
    CP_WAIT0();
    __syncthreads();

    const int NCH = H / BKC;   // 8
    for (int c = 0; c < NCH; c++) {
        const int buf = c & 1;
        const uint32_t base = sbase + buf * GH_BUFB;

        if (c + 1 < NCH) cpAB(c + 1, buf ^ 1);

        #pragma unroll
        for (int ks = 0; ks < 4; ks++) {
            const uint32_t kb = ks * 32;
            uint32_t fa[4][4];
            #pragma unroll
            for (int mt = 0; mt < 4; mt++)
                ldmx4(fa[mt][0], fa[mt][1], fa[mt][2], fa[mt][3],
                      base + GH_OFF_A + a_lm + mt * 16 * PITCH + kb);

            uint32_t bh[8];
            ldmx4(bh[0], bh[1], bh[2], bh[3], base + GH_OFF_B + b_lm4[0] + kb);
            ldmx4(bh[4], bh[5], bh[6], bh[7], base + GH_OFF_B + b_lm4[1] + kb);

            #pragma unroll
            for (int nt = 0; nt < 4; nt++) {
                uint32_t h0 = bh[2*nt], h1 = bh[2*nt+1];
                #pragma unroll
                for (int mt = 0; mt < 4; mt++) {
                    float* d = acc[mt][nt];
                    mma16816(d[0],d[1],d[2],d[3],
                             fa[mt][0],fa[mt][1],fa[mt][2],fa[mt][3], h0, h1);
                }
            }
        }

        if (c + 1 < NCH) {
            CP_WAIT0();
            __syncthreads();
        }
    }

    // epilogue: relu + Wg2 dot, quad-reduce, atomic partial per row
    #pragma unroll
    for (int mt = 0; mt < 4; mt++) {
        #pragma unroll
        for (int half = 0; half < 2; half++) {
            int row = brow + wm * 64 + mt * 16 + g + half * 8;
            float p = 0.f;
            #pragma unroll
            for (int nt = 0; nt < 4; nt++) {
                int col = wn * 32 + nt * 8 + 2 * t;    // local col in [0,128)
                float v0 = acc[mt][nt][2 * half + 0] + s_bg1[col];
                float v1 = acc[mt][nt][2 * half + 1] + s_bg1[col + 1];
                v0 = v0 > 0.f ? v0 : 0.f;
                v1 = v1 > 0.f ? v1 : 0.f;
                p = fmaf(v0, s_wg2[col], p);
                p = fmaf(v1, s_wg2[col + 1], p);
            }
            p += __shfl_down_sync(0xffffffffu, p, 2, 4);
            p += __shfl_down_sync(0xffffffffu, p, 1, 4);
            if (t == 0 && row < B) atomicAdd(&graph_out[row], p);
        }
    }
}

// ---------------------------------------------------------------------------
// Kernel 4: edge head
// ---------------------------------------------------------------------------
__global__ __launch_bounds__(256)
void edge_head(const int* __restrict__ edge_index,
               const int* __restrict__ rev,
               float* __restrict__ edge_out,
               int E)
{
    int k = blockIdx.x * blockDim.x + threadIdx.x;
    int half = E >> 1;
    if (k >= half) return;
    int e = 2 * k;
    if (!(e < rev[e])) e = 2 * k + 1;
    int a1 = edge_index[e];
    int a2 = edge_index[E + e];
    const float2* p1 = reinterpret_cast<const float2*>(g_atom_proj + (size_t)a1 * BF);
    const float2* p2 = reinterpret_cast<const float2*>(g_atom_proj + (size_t)a2 * BF);
    float2* o = reinterpret_cast<float2*>(edge_out + (size_t)k * BF);
    #pragma unroll
    for (int c = 0; c < BF / 2; c++) {
        float2 u = p1[c], v = p2[c];
        float2 r;
        r.x = 0.5f * (u.x + v.x);
        r.y = 0.5f * (u.y + v.y);
        o[c] = r;
    }
}

// ---------------------------------------------------------------------------
extern "C" void kernel_launch(void* const* d_in, const int* in_sizes, int n_in,
                              void* d_out, int out_size)
{
    const float* A    = (const float*)d_in[0];
    const float* Wn   = (const float*)d_in[1];
    const float* bn   = (const float*)d_in[2];
    const float* We   = (const float*)d_in[3];
    const float* be   = (const float*)d_in[4];
    const float* Wg1  = (const float*)d_in[5];
    const float* bg1  = (const float*)d_in[6];
    const float* Wg2  = (const float*)d_in[7];
    const float* bg2  = (const float*)d_in[8];
    const int* edge_index = (const int*)d_in[9];
    const int* rev        = (const int*)d_in[10];
    const int* batch      = (const int*)d_in[11];

    const int N = in_sizes[0] / H;
    const int E = in_sizes[9] / 2;
    const int half = E / 2;
    const int B = out_size - N * AF - half * BF;

    float* out = (float*)d_out;
    float* node_out  = out;
    float* edge_out  = out + (size_t)N * AF;
    float* graph_out = out + (size_t)N * AF + (size_t)half * BF;

    cudaFuncSetAttribute(gemm_mma, cudaFuncAttributeMaxDynamicSharedMemorySize, SMEM_DYN);
    cudaFuncSetAttribute(graph_head_mma, cudaFuncAttributeMaxDynamicSharedMemorySize, GH_SMEM);

    static cudaStream_t s2 = nullptr;
    static cudaEvent_t ev_fork = nullptr, ev_join = nullptr;
    if (s2 == nullptr) {
        cudaStreamCreateWithFlags(&s2, cudaStreamNonBlocking);
        cudaEventCreateWithFlags(&ev_fork, cudaEventDisableTiming);
        cudaEventCreateWithFlags(&ev_join, cudaEventDisableTiming);
    }

    // main: pack_all -> pool_convert -> [fork] -> gemm -> edge
    pack_all<<<(PACK_TOTAL + 255) / 256, 256>>>(Wn, We, Wg1);              // 0
    pool_convert<<<B, 128>>>(A, batch, N);                                 // 1

    cudaEventRecord(ev_fork, 0);
    cudaStreamWaitEvent(s2, ev_fork, 0);

    init_graph_out<<<(B + 255) / 256, 256, 0, s2>>>(graph_out, bg2, B);    // 2 (s2)
    gemm_mma<<<(N + BM - 1) / BM, GT, SMEM_DYN>>>(bn, be, node_out, N);    // 3 (main, ncu slot)
    graph_head_mma<<<dim3((B + 127) / 128, 4), 256, GH_SMEM, s2>>>(bg1, Wg2, graph_out, B); // 4 (s2)
    edge_head<<<(half + 255) / 256, 256>>>(edge_index, rev, edge_out, E);  // 5 (main)

    cudaEventRecord(ev_join, s2);
    cudaStreamWaitEvent(0, ev_join, 0);
}

// round 17
// speedup vs baseline: 1.4197x; 1.0591x over previous
#include <cuda_runtime.h>
#include <cuda_fp16.h>
#include <cuda_bf16.h>
#include <cstdint>

// ---------------------------------------------------------------------------
// SSLPretrainModel v14 — single-pass mega-fusion:
//   gemm_all: reads fp32 A once (cp.async), converts fp32->fp16 in smem,
//             runs HMMA GEMM (node+edge proj), AND pools per-graph sums
//             from the resident fp16 tile (atomicAdd into zeroed emb32).
//   Then: emb_to16 -> graph_head_mma (HMMA)  ||  edge_head.
//   rel_err ~3e-4 << 1e-3.
// ---------------------------------------------------------------------------

#define H 512
#define AF 133
#define BF 14
#define NCOLS (AF + BF)      // 147
#define NPAD 160

#define MAX_N 204800
#define MAX_B 4608

__device__ float g_atom_proj[MAX_N * BF];
__device__ float g_emb32[MAX_B * H];
__device__ __align__(16) __half g_Wh[NPAD * H];     // fused W^T fp16 [160][512]
__device__ __align__(16) __half g_Wg1h[H * H];      // Wg1^T fp16 [512][512]
__device__ __align__(16) __half g_emb16[MAX_B * H];

// ---------------------------------------------------------------------------
// helpers
// ---------------------------------------------------------------------------
__device__ __forceinline__ uint32_t smem_u32(const void* p) {
    uint32_t a;
    asm("{ .reg .u64 t; cvta.to.shared.u64 t, %1; cvt.u32.u64 %0, t; }" : "=r"(a) : "l"(p));
    return a;
}

__device__ __forceinline__ uint32_t f16x2_pack(float lo_elem, float hi_elem) {
    uint32_t r;
    asm("cvt.rn.f16x2.f32 %0, %1, %2;" : "=r"(r) : "f"(hi_elem), "f"(lo_elem));
    return r;
}

__device__ __forceinline__ void mma16816(float& d0, float& d1, float& d2, float& d3,
                                         uint32_t a0, uint32_t a1, uint32_t a2, uint32_t a3,
                                         uint32_t b0, uint32_t b1) {
    asm volatile(
        "mma.sync.aligned.m16n8k16.row.col.f32.f16.f16.f32 "
        "{%0,%1,%2,%3}, {%4,%5,%6,%7}, {%8,%9}, {%0,%1,%2,%3};"
        : "+f"(d0), "+f"(d1), "+f"(d2), "+f"(d3)
        : "r"(a0), "r"(a1), "r"(a2), "r"(a3), "r"(b0), "r"(b1));
}

__device__ __forceinline__ void ldmx4(uint32_t& r0, uint32_t& r1, uint32_t& r2,
                                      uint32_t& r3, uint32_t addr) {
    asm volatile("ldmatrix.sync.aligned.m8n8.x4.shared.b16 {%0,%1,%2,%3}, [%4];"
                 : "=r"(r0), "=r"(r1), "=r"(r2), "=r"(r3) : "r"(addr));
}
__device__ __forceinline__ void ldmx2(uint32_t& r0, uint32_t& r1, uint32_t addr) {
    asm volatile("ldmatrix.sync.aligned.m8n8.x2.shared.b16 {%0,%1}, [%2];"
                 : "=r"(r0), "=r"(r1) : "r"(addr));
}

#define CP_ASYNC16(saddr, gptr) \
    asm volatile("cp.async.cg.shared.global [%0], [%1], 16;" :: "r"(saddr), "l"(gptr))
#define CP_COMMIT() asm volatile("cp.async.commit_group;" ::: "memory")
#define CP_WAIT0()  asm volatile("cp.async.wait_group 0;" ::: "memory")

// ---------------------------------------------------------------------------
// Kernel 0: pack ALL weights to fp16 (fused W^T and Wg1^T).
// ---------------------------------------------------------------------------
#define PACK_TOTAL (NPAD * H + H * H)

__global__ void pack_all(const float* __restrict__ Wn,
                         const float* __restrict__ We,
                         const float* __restrict__ Wg1)
{
    int idx = blockIdx.x * 256 + threadIdx.x;
    if (idx >= PACK_TOTAL) return;
    if (idx < NPAD * H) {
        int n = idx >> 9;
        int k = idx & 511;
        float v = 0.f;
        if (n < AF)         v = Wn[k * AF + n];
        else if (n < NCOLS) v = We[k * BF + (n - AF)];
        g_Wh[idx] = __float2half_rn(v);
    } else {
        int j = idx - NPAD * H;
        int n = j >> 9;
        int k = j & 511;
        g_Wg1h[j] = __float2half_rn(Wg1[k * H + n]);
    }
}

// ---------------------------------------------------------------------------
// Kernel 1: zero fp32 emb accumulator
// ---------------------------------------------------------------------------
__global__ void zero_emb(int B)
{
    int i = blockIdx.x * 256 + threadIdx.x;
    if (i < B * (H / 4))
        reinterpret_cast<float4*>(g_emb32)[i] = make_float4(0.f, 0.f, 0.f, 0.f);
}

// ---------------------------------------------------------------------------
// Kernel 2: mega-fused GEMM. CTA 64x160, 256 threads, 2 CTAs/SM, BK=64.
//   - cp.async fp32 A (double-buffered) + fp16 W (double-buffered)
//   - smem convert pass fp32->fp16
//   - HMMA mainloop (warp grid 2m x 4n, tile 32x40)
//   - per-chunk segmented column-sum pooling (atomicAdd to g_emb32)
// ---------------------------------------------------------------------------
#define BKC 64
#define PITCH 144                          // fp16 tile pitch (128B data + 16 pad)
#define P32 272                            // fp32 tile pitch (256B data + 16 pad)
#define BM 64
#define A32_T (BM * P32)                   // 17408
#define A16_T (BM * PITCH)                 // 9216
#define BW_T  (160 * PITCH)                // 23040
#define OFF_A32(b) ((b) * A32_T)
#define OFF_A16(b) (2 * A32_T + (b) * A16_T)
#define OFF_BB(b)  (2 * A32_T + 2 * A16_T + (b) * BW_T)
#define SMEM_DYN (2 * A32_T + 2 * A16_T + 2 * BW_T)   // 99328
#define GT 256

__global__ __launch_bounds__(GT, 2)
void gemm_all(const float* __restrict__ A,
              const int* __restrict__ batch,
              const float* __restrict__ bn,
              const float* __restrict__ be,
              float* __restrict__ node_out,
              int N)
{
    extern __shared__ char dyn[];
    __shared__ float s_bias[NPAD];
    __shared__ int s_batch[BM];

    const int tid = threadIdx.x;
    const int wid = tid >> 5;
    const int lid = tid & 31;
    const int block_row = blockIdx.x * BM;
    const uint32_t sbase = smem_u32(dyn);

    if (tid < NPAD) {
        float b = 0.f;
        if (tid < AF) b = bn[tid];
        else if (tid < NCOLS) b = be[tid - AF];
        s_bias[tid] = b;
    }
    if (tid < BM) {
        int row = block_row + tid;
        s_batch[tid] = (row < N) ? batch[row] : -1;
    }

    // A32 cp.async: 64 rows x 256B = 1024 x 16B -> 4 per thread
    const float* a32src[4];
    uint32_t a32smem[4];
    bool aact[4];
    #pragma unroll
    for (int i = 0; i < 4; i++) {
        int idx = tid + i * GT;
        int r = idx >> 4;                  // 0..63
        int j = idx & 15;                  // 0..15 (16B = 4 floats)
        aact[i]   = (block_row + r < N);
        a32src[i] = A + (size_t)(block_row + r) * H + j * 4;
        a32smem[i] = (uint32_t)(r * P32 + j * 16);
    }
    // B cp.async: 160 rows x 128B = 1280 x 16B -> 5 per thread
    const __half* bsrc[5];
    uint32_t bsmem[5];
    #pragma unroll
    for (int i = 0; i < 5; i++) {
        int idx = tid + i * GT;
        int r = idx >> 3;
        int j = idx & 7;
        bsrc[i]  = g_Wh + (size_t)r * H + j * 8;
        bsmem[i] = (uint32_t)(r * PITCH + j * 16);
    }

    auto cpAB = [&](int c, int buf) {
        const uint32_t a32b = sbase + OFF_A32(buf);
        const uint32_t bb   = sbase + OFF_BB(buf);
        #pragma unroll
        for (int i = 0; i < 4; i++)
            if (aact[i]) CP_ASYNC16(a32b + a32smem[i], a32src[i] + c * BKC);
        #pragma unroll
        for (int i = 0; i < 5; i++)
            CP_ASYNC16(bb + bsmem[i], bsrc[i] + c * BKC);
        CP_COMMIT();
    };

    // convert pass: fp32 tile -> fp16 tile (16 floats per thread)
    const int cv_r  = tid >> 2;            // 0..63
    const int cv_jq = tid & 3;             // 0..3 (16-float groups)
    auto convert = [&](int buf) {
        const char* src = dyn + OFF_A32(buf) + cv_r * P32 + cv_jq * 64;
        float4 f0 = *reinterpret_cast<const float4*>(src);
        float4 f1 = *reinterpret_cast<const float4*>(src + 16);
        float4 f2 = *reinterpret_cast<const float4*>(src + 32);
        float4 f3 = *reinterpret_cast<const float4*>(src + 48);
        uint4 o0 = make_uint4(f16x2_pack(f0.x, f0.y), f16x2_pack(f0.z, f0.w),
                              f16x2_pack(f1.x, f1.y), f16x2_pack(f1.z, f1.w));
        uint4 o1 = make_uint4(f16x2_pack(f2.x, f2.y), f16x2_pack(f2.z, f2.w),
                              f16x2_pack(f3.x, f3.y), f16x2_pack(f3.z, f3.w));
        char* dst = dyn + OFF_A16(buf) + cv_r * PITCH + cv_jq * 32;
        *reinterpret_cast<uint4*>(dst)      = o0;
        *reinterpret_cast<uint4*>(dst + 16) = o1;
    };

    // pooling pass: thread -> col j (0..63), quarter q (16 rows)
    const int pl_j = tid & 63;
    const int pl_q = tid >> 6;
    auto pool = [&](int buf, int c) {
        float s = 0.f;
        int cur = s_batch[pl_q * 16];
        #pragma unroll
        for (int rr = 0; rr < 16; rr++) {
            int r = pl_q * 16 + rr;
            int bb = s_batch[r];
            if (bb != cur) {
                if (cur >= 0)
                    atomicAdd(&g_emb32[(size_t)cur * H + c * 64 + pl_j], s);
                s = 0.f;
                cur = bb;
            }
            __half h = *reinterpret_cast<const __half*>(
                dyn + OFF_A16(buf) + r * PITCH + pl_j * 2);
            s += __half2float(h);
        }
        if (cur >= 0)
            atomicAdd(&g_emb32[(size_t)cur * H + c * 64 + pl_j], s);
    };

    // accumulators: warp tile 32(m) x 40(n)
    float acc[2][5][4];
    #pragma unroll
    for (int mt = 0; mt < 2; mt++)
        #pragma unroll
        for (int nt = 0; nt < 5; nt++)
            #pragma unroll
            for (int q = 0; q < 4; q++) acc[mt][nt][q] = 0.f;

    const int wm = wid & 1;
    const int wn = wid >> 1;
    const int g  = lid >> 2;
    const int t  = lid & 3;
    const int lid16 = lid & 15;

    const uint32_t a_lm0 = (uint32_t)((wm * 32 + lid16) * PITCH + (lid >> 4) * 16);
    const uint32_t a_lm1 = a_lm0 + 16 * PITCH;
    uint32_t b_lm4[2];
    #pragma unroll
    for (int p = 0; p < 2; p++)
        b_lm4[p] = (uint32_t)((wn * 40 + p * 16 + (lid & 7) + ((lid >> 4) & 1) * 8) * PITCH
                              + ((lid >> 3) & 1) * 16);
    const uint32_t b_lm2 = (uint32_t)((wn * 40 + 32 + (lid16 & 7)) * PITCH
                                      + ((lid16 >> 3) & 1) * 16);

    // prologue: load chunk 0, convert it
    cpAB(0, 0);
    CP_WAIT0();
    __syncthreads();
    convert(0);

    const int NCH = H / BKC;   // 8
    for (int c = 0; c < NCH; c++) {
        const int buf = c & 1;
        const uint32_t a16b = sbase + OFF_A16(buf);
        const uint32_t bwb  = sbase + OFF_BB(buf);

        if (c + 1 < NCH) cpAB(c + 1, buf ^ 1);
        __syncthreads();                 // convert(c) results visible

        #pragma unroll
        for (int ks = 0; ks < 4; ks++) {
            const uint32_t kb = ks * 32;
            uint32_t fah[2][4];
            ldmx4(fah[0][0], fah[0][1], fah[0][2], fah[0][3], a16b + a_lm0 + kb);
            ldmx4(fah[1][0], fah[1][1], fah[1][2], fah[1][3], a16b + a_lm1 + kb);

            uint32_t bh[10];
            ldmx4(bh[0], bh[1], bh[2], bh[3], bwb + b_lm4[0] + kb);
            ldmx4(bh[4], bh[5], bh[6], bh[7], bwb + b_lm4[1] + kb);
            ldmx2(bh[8], bh[9],              bwb + b_lm2 + kb);

            #pragma unroll
            for (int nt = 0; nt < 5; nt++) {
                uint32_t h0 = bh[2*nt], h1 = bh[2*nt+1];
                #pragma unroll
                for (int mt = 0; mt < 2; mt++) {
                    float* d = acc[mt][nt];
                    mma16816(d[0],d[1],d[2],d[3],
                             fah[mt][0],fah[mt][1],fah[mt][2],fah[mt][3], h0, h1);
                }
            }
        }

        pool(buf, c);

        if (c + 1 < NCH) {
            CP_WAIT0();
            __syncthreads();             // chunk c+1 fp32/B landed; A16[buf^1] free
            convert(buf ^ 1);            // fp32(c+1) -> fp16[buf^1]
        }
    }

    // epilogue: bias + split node/proj stores
    #pragma unroll
    for (int mt = 0; mt < 2; mt++) {
        #pragma unroll
        for (int half = 0; half < 2; half++) {
            int row = block_row + wm * 32 + mt * 16 + g + half * 8;
            if (row >= N) continue;
            float* nrow = node_out + (size_t)row * AF;
            float* prow = g_atom_proj + (size_t)row * BF;
            #pragma unroll
            for (int nt = 0; nt < 5; nt++) {
                int col = wn * 40 + nt * 8 + 2 * t;
                float v0 = acc[mt][nt][2 * half + 0] + s_bias[col];
                float v1 = acc[mt][nt][2 * half + 1] + s_bias[col + 1];
                if (col < AF)          nrow[col] = v0;
                else if (col < NCOLS)  prow[col - AF] = v0;
                if (col + 1 < AF)          nrow[col + 1] = v1;
                else if (col + 1 < NCOLS)  prow[col + 1 - AF] = v1;
            }
        }
    }
}

// ---------------------------------------------------------------------------
// Kernel 3: emb fp32 -> fp16
// ---------------------------------------------------------------------------
__global__ void emb_to16(int B)
{
    int i = blockIdx.x * 256 + threadIdx.x;
    if (i < B * (H / 4)) {
        float4 v = reinterpret_cast<const float4*>(g_emb32)[i];
        reinterpret_cast<uint2*>(g_emb16)[i] =
            make_uint2(f16x2_pack(v.x, v.y), f16x2_pack(v.z, v.w));
    }
}

// ---------------------------------------------------------------------------
// Kernel 4a: init graph output with b_g2
// ---------------------------------------------------------------------------
__global__ void init_graph_out(float* __restrict__ graph_out,
                               const float* __restrict__ bg2, int B)
{
    int g = blockIdx.x * blockDim.x + threadIdx.x;
    if (g < B) graph_out[g] = bg2[0];
}

// ---------------------------------------------------------------------------
// Kernel 4b: graph head on HMMA (CTA 128x128, relu + Wg2 dot fused).
// ---------------------------------------------------------------------------
#define GH_A_TILE (128 * PITCH)
#define GH_B_TILE (128 * PITCH)
#define GH_OFF_A 0
#define GH_OFF_B (GH_A_TILE)
#define GH_BUFB (GH_A_TILE + GH_B_TILE)
#define GH_SMEM (2 * GH_BUFB)

__global__ __launch_bounds__(256, 2)
void graph_head_mma(const float* __restrict__ bg1,
                    const float* __restrict__ Wg2,
                    float* __restrict__ graph_out,
                    int B)
{
    extern __shared__ char dyn[];
    __shared__ float s_bg1[128];
    __shared__ float s_wg2[128];

    const int tid = threadIdx.x;
    const int wid = tid >> 5;
    const int lid = tid & 31;
    const int brow = blockIdx.x * 128;
    const int bcol = blockIdx.y * 128;
    const uint32_t sbase = smem_u32(dyn);

    if (tid < 128) {
        s_bg1[tid] = bg1[bcol + tid];
        s_wg2[tid] = Wg2[bcol + tid];
    }

    const __half* asrc[4];
    uint32_t asmem[4];
    bool aact[4];
    #pragma unroll
    for (int i = 0; i < 4; i++) {
        int idx = tid + i * 256;
        int r = idx >> 3;
        int j = idx & 7;
        aact[i]  = (brow + r < B);
        asrc[i]  = g_emb16 + (size_t)(brow + r) * H + j * 8;
        asmem[i] = (uint32_t)(GH_OFF_A + r * PITCH + j * 16);
    }
    const __half* bsrc[4];
    uint32_t bsmem[4];
    #pragma unroll
    for (int i = 0; i < 4; i++) {
        int idx = tid + i * 256;
        int r = idx >> 3;
        int j = idx & 7;
        bsrc[i]  = g_Wg1h + (size_t)(bcol + r) * H + j * 8;
        bsmem[i] = (uint32_t)(GH_OFF_B + r * PITCH + j * 16);
    }

    auto cpAB = [&](int c, int buf) {
        const uint32_t bb = sbase + buf * GH_BUFB;
        #pragma unroll
        for (int i = 0; i < 4; i++)
            if (aact[i]) CP_ASYNC16(bb + asmem[i], asrc[i] + c * BKC);
        #pragma unroll
        for (int i = 0; i < 4; i++)
            CP_ASYNC16(bb + bsmem[i], bsrc[i] + c * BKC);
        CP_COMMIT();
    };

    float acc[4][4][4];
    #pragma unroll
    for (int mt = 0; mt < 4; mt++)
        #pragma unroll
        for (int nt = 0; nt < 4; nt++)
            #pragma unroll
            for (int q = 0; q < 4; q++) acc[mt][nt][q] = 0.f;

    const int wm = wid & 1;
    const int wn = wid >> 1;
    const int g  = lid >> 2;
    const int t  = lid & 3;
    const int lid16 = lid & 15;

    const uint32_t a_lm = (uint32_t)((wm * 64 + lid16) * PITCH + (lid >> 4) * 16);
    uint32_t b_lm4[2];
    #pragma unroll
    for (int p = 0; p < 2; p++)
        b_lm4[p] = (uint32_t)((wn * 32 + p * 16 + (lid & 7) + ((lid >> 4) & 1) * 8) * PITCH
                              + ((lid >> 3) & 1) * 16);

    cpAB(0, 0);
    CP_WAIT0();
    __syncthreads();

    const int NCH = H / BKC;
    for (int c = 0; c < NCH; c++) {
        const int buf = c & 1;
        const uint32_t base = sbase + buf * GH_BUFB;

        if (c + 1 < NCH) cpAB(c + 1, buf ^ 1);

        #pragma unroll
        for (int ks = 0; ks < 4; ks++) {
            const uint32_t kb = ks * 32;
            uint32_t fa[4][4];
            #pragma unroll
            for (int mt = 0; mt < 4; mt++)
                ldmx4(fa[mt][0], fa[mt][1], fa[mt][2], fa[mt][3],
                      base + GH_OFF_A + a_lm + mt * 16 * PITCH + kb);

            uint32_t bh[8];
            ldmx4(bh[0], bh[1], bh[2], bh[3], base + GH_OFF_B + b_lm4[0] + kb);
            ldmx4(bh[4], bh[5], bh[6], bh[7], base + GH_OFF_B + b_lm4[1] + kb);

            #pragma unroll
            for (int nt = 0; nt < 4; nt++) {
                uint32_t h0 = bh[2*nt], h1 = bh[2*nt+1];
                #pragma unroll
                for (int mt = 0; mt < 4; mt++) {
                    float* d = acc[mt][nt];
                    mma16816(d[0],d[1],d[2],d[3],
                             fa[mt][0],fa[mt][1],fa[mt][2],fa[mt][3], h0, h1);
                }
            }
        }

        if (c + 1 < NCH) {
            CP_WAIT0();
            __syncthreads();
        }
    }

    #pragma unroll
    for (int mt = 0; mt < 4; mt++) {
        #pragma unroll
        for (int half = 0; half < 2; half++) {
            int row = brow + wm * 64 + mt * 16 + g + half * 8;
            float p = 0.f;
            #pragma unroll
            for (int nt = 0; nt < 4; nt++) {
                int col = wn * 32 + nt * 8 + 2 * t;
                float v0 = acc[mt][nt][2 * half + 0] + s_bg1[col];
                float v1 = acc[mt][nt][2 * half + 1] + s_bg1[col + 1];
                v0 = v0 > 0.f ? v0 : 0.f;
                v1 = v1 > 0.f ? v1 : 0.f;
                p = fmaf(v0, s_wg2[col], p);
                p = fmaf(v1, s_wg2[col + 1], p);
            }
            p += __shfl_down_sync(0xffffffffu, p, 2, 4);
            p += __shfl_down_sync(0xffffffffu, p, 1, 4);
            if (t == 0 && row < B) atomicAdd(&graph_out[row], p);
        }
    }
}

// ---------------------------------------------------------------------------
// Kernel 5: edge head
// ---------------------------------------------------------------------------
__global__ __launch_bounds__(256)
void edge_head(const int* __restrict__ edge_index,
               const int* __restrict__ rev,
               float* __restrict__ edge_out,
               int E)
{
    int k = blockIdx.x * blockDim.x + threadIdx.x;
    int half = E >> 1;
    if (k >= half) return;
    int e = 2 * k;
    if (!(e < rev[e])) e = 2 * k + 1;
    int a1 = edge_index[e];
    int a2 = edge_index[E + e];
    const float2* p1 = reinterpret_cast<const float2*>(g_atom_proj + (size_t)a1 * BF);
    const float2* p2 = reinterpret_cast<const float2*>(g_atom_proj + (size_t)a2 * BF);
    float2* o = reinterpret_cast<float2*>(edge_out + (size_t)k * BF);
    #pragma unroll
    for (int c = 0; c < BF / 2; c++) {
        float2 u = p1[c], v = p2[c];
        float2 r;
        r.x = 0.5f * (u.x + v.x);
        r.y = 0.5f * (u.y + v.y);
        o[c] = r;
    }
}

// ---------------------------------------------------------------------------
extern "C" void kernel_launch(void* const* d_in, const int* in_sizes, int n_in,
                              void* d_out, int out_size)
{
    const float* A    = (const float*)d_in[0];
    const float* Wn   = (const float*)d_in[1];
    const float* bn   = (const float*)d_in[2];
    const float* We   = (const float*)d_in[3];
    const float* be   = (const float*)d_in[4];
    const float* Wg1  = (const float*)d_in[5];
    const float* bg1  = (const float*)d_in[6];
    const float* Wg2  = (const float*)d_in[7];
    const float* bg2  = (const float*)d_in[8];
    const int* edge_index = (const int*)d_in[9];
    const int* rev        = (const int*)d_in[10];
    const int* batch      = (const int*)d_in[11];

    const int N = in_sizes[0] / H;
    const int E = in_sizes[9] / 2;
    const int half = E / 2;
    const int B = out_size - N * AF - half * BF;

    float* out = (float*)d_out;
    float* node_out  = out;
    float* edge_out  = out + (size_t)N * AF;
    float* graph_out = out + (size_t)N * AF + (size_t)half * BF;

    cudaFuncSetAttribute(gemm_all, cudaFuncAttributeMaxDynamicSharedMemorySize, SMEM_DYN);
    cudaFuncSetAttribute(graph_head_mma, cudaFuncAttributeMaxDynamicSharedMemorySize, GH_SMEM);

    static cudaStream_t s2 = nullptr;
    static cudaEvent_t ev_fork = nullptr, ev_join = nullptr;
    if (s2 == nullptr) {
        cudaStreamCreateWithFlags(&s2, cudaStreamNonBlocking);
        cudaEventCreateWithFlags(&ev_fork, cudaEventDisableTiming);
        cudaEventCreateWithFlags(&ev_join, cudaEventDisableTiming);
    }

    // main: pack -> zero emb -> init graph_out -> mega gemm (ncu slot 3)
    pack_all<<<(PACK_TOTAL + 255) / 256, 256>>>(Wn, We, Wg1);              // 0
    zero_emb<<<(B * (H / 4) + 255) / 256, 256>>>(B);                       // 1
    init_graph_out<<<(B + 255) / 256, 256>>>(graph_out, bg2, B);           // 2
    gemm_all<<<(N + BM - 1) / BM, GT, SMEM_DYN>>>(A, batch, bn, be, node_out, N); // 3

    // after gemm: s2 does emb16 + head, main does edge (concurrent tails)
    cudaEventRecord(ev_fork, 0);
    cudaStreamWaitEvent(s2, ev_fork, 0);
    emb_to16<<<(B * (H / 4) + 255) / 256, 256, 0, s2>>>(B);
    graph_head_mma<<<dim3((B + 127) / 128, 4), 256, GH_SMEM, s2>>>(bg1, Wg2, graph_out, B);
    edge_head<<<(half + 255) / 256, 256>>>(edge_index, rev, edge_out, E);

    cudaEventRecord(ev_join, s2);
    cudaStreamWaitEvent(0, ev_join, 0);
}